// round 1
// baseline (speedup 1.0000x reference)
#include <cuda_runtime.h>
#include <cstddef>

// Shapes (fixed by the problem)
#define NB 16
#define NM 128
#define NH 256
#define NE 128
#define NC (NH + NE)      // 384
#define NROWS (NB * NM)   // 2048

// Scratch (static device arrays: allocation-free rule)
__device__ float g_msg[NROWS * NC];   // (2048, 384): [msg_x(256) | msg_e(128)]
__device__ float g_t[NROWS * NH];     // after Wr residual stage
__device__ float g_u[NROWS * NH];     // after W0 stage

// ---------------------------------------------------------------------------
// f32x2 packed-FMA helpers (Blackwell): exact fp32 semantics, 2 FMAs/instr
// ---------------------------------------------------------------------------
__device__ __forceinline__ unsigned long long pack_dup(float x) {
    unsigned long long r;
    asm("mov.b64 %0, {%1, %1};" : "=l"(r) : "f"(x));
    return r;
}
__device__ __forceinline__ unsigned long long fma2(unsigned long long a,
                                                   unsigned long long b,
                                                   unsigned long long c) {
    unsigned long long d;
    asm("fma.rn.f32x2 %0, %1, %2, %3;" : "=l"(d) : "l"(a), "l"(b), "l"(c));
    return d;
}
__device__ __forceinline__ float2 unpack2(unsigned long long v) {
    float2 f;
    asm("mov.b64 {%0, %1}, %2;" : "=f"(f.x), "=f"(f.y) : "l"(v));
    return f;
}

// ---------------------------------------------------------------------------
// Kernel A (the hot one): fused edge-mapper GEMM + A-weighted reduce over i.
//   For a fixed (b, j):
//     Em[i,f] = relu(sum_e E[b,i,j,e] * We[e,f] + be[f])       (128x128x128)
//     msg_e[f] = sum_i A[b,i,j] * Em[i,f]
//   Em never leaves registers.
// grid = 2048 (b*128+j), block = 256 threads (16 f-groups x 16 i-groups)
// Thread tile: 8 i x 8 f, i packed in pairs for f32x2.
// ---------------------------------------------------------------------------
__global__ __launch_bounds__(256, 2)
void edge_msg_kernel(const float* __restrict__ E,
                     const float* __restrict__ A,
                     const float* __restrict__ We,
                     const float* __restrict__ be,
                     float* __restrict__ msg)
{
    const int bj  = blockIdx.x;
    const int b   = bj >> 7;
    const int j   = bj & 127;
    const int tid = threadIdx.x;
    const int tx  = tid & 15;   // f group: f = tx*8 .. tx*8+7
    const int ty  = tid >> 4;   // i group: i = ty*8 .. ty*8+7

    __shared__ float Es[16][132];    // [e_local][i]  (132: 16B-aligned rows, pad)
    __shared__ float Ws[16][128];    // [e_local][f]
    __shared__ float Aw[128];        // A[b, i, j]
    __shared__ float red[16][128];   // cross-i-group reduction

    // Per-(b,j) column of A (strided gather, once per CTA)
    if (tid < 128) Aw[tid] = A[(b * 128 + tid) * 128 + j];

    const float* Eb = E + ((size_t)(b * 128) * 128 + j) * 128;  // + i*16384 + e

    // acc2[rp][c]: packed pair over i = (ty*8+2rp, ty*8+2rp+1), column f = tx*8+c
    unsigned long long acc2[4][8];
    #pragma unroll
    for (int rp = 0; rp < 4; ++rp)
        #pragma unroll
        for (int c = 0; c < 8; ++c) acc2[rp][c] = 0ull;

    for (int ke = 0; ke < 128; ke += 16) {
        // Load E tile (128 i x 16 e), transposed into Es[e][i]
        #pragma unroll
        for (int it = 0; it < 2; ++it) {
            int idx = tid + it * 256;          // 0..511
            int i   = idx & 127;
            int e4  = idx >> 7;                // 0..3
            float4 v = *(const float4*)(Eb + (size_t)i * 16384 + ke + e4 * 4);
            Es[e4 * 4 + 0][i] = v.x;
            Es[e4 * 4 + 1][i] = v.y;
            Es[e4 * 4 + 2][i] = v.z;
            Es[e4 * 4 + 3][i] = v.w;
        }
        // Load We tile (16 e x 128 f)
        #pragma unroll
        for (int it = 0; it < 2; ++it) {
            int idx = tid + it * 256;          // 0..511
            int el  = idx >> 5;                // 0..15
            int f4  = idx & 31;                // 0..31
            *(float4*)&Ws[el][f4 * 4] =
                *(const float4*)(We + (ke + el) * 128 + f4 * 4);
        }
        __syncthreads();

        #pragma unroll
        for (int kk = 0; kk < 16; ++kk) {
            // a-frag: 8 consecutive i values = 4 natural f32 pairs
            const ulonglong2* ap = (const ulonglong2*)&Es[kk][ty * 8];
            ulonglong2 a01 = ap[0];
            ulonglong2 a23 = ap[1];
            unsigned long long a2[4] = {a01.x, a01.y, a23.x, a23.y};
            // b-frag: 8 f values, duplicated into both halves
            float bb[8];
            *(float4*)&bb[0] = *(const float4*)&Ws[kk][tx * 8];
            *(float4*)&bb[4] = *(const float4*)&Ws[kk][tx * 8 + 4];
            unsigned long long bd[8];
            #pragma unroll
            for (int c = 0; c < 8; ++c) bd[c] = pack_dup(bb[c]);
            #pragma unroll
            for (int rp = 0; rp < 4; ++rp)
                #pragma unroll
                for (int c = 0; c < 8; ++c)
                    acc2[rp][c] = fma2(a2[rp], bd[c], acc2[rp][c]);
        }
        __syncthreads();
    }

    // Epilogue: bias + relu, weight by A, partial-reduce over this thread's 8 i's
    float bias[8];
    #pragma unroll
    for (int c = 0; c < 8; ++c) bias[c] = be[tx * 8 + c];

    float part[8];
    #pragma unroll
    for (int c = 0; c < 8; ++c) part[c] = 0.f;

    #pragma unroll
    for (int rp = 0; rp < 4; ++rp) {
        float w0 = Aw[ty * 8 + 2 * rp];
        float w1 = Aw[ty * 8 + 2 * rp + 1];
        #pragma unroll
        for (int c = 0; c < 8; ++c) {
            float2 v = unpack2(acc2[rp][c]);
            part[c] += w0 * fmaxf(v.x + bias[c], 0.f)
                     + w1 * fmaxf(v.y + bias[c], 0.f);
        }
    }

    // Cross-i-group reduce (16 groups)
    #pragma unroll
    for (int c = 0; c < 8; ++c) red[ty][tx * 8 + c] = part[c];
    __syncthreads();
    if (tid < 128) {
        float s = 0.f;
        #pragma unroll
        for (int g = 0; g < 16; ++g) s += red[g][tid];
        msg[(size_t)bj * NC + NH + tid] = s;   // msg_e slot
    }
}

// ---------------------------------------------------------------------------
// Kernel B: msg_x[b,j,h] = sum_i A[b,i,j] * X[b,i,h]
// grid = 16 b x 8 j-tiles = 128 blocks, 256 threads (thread = h)
// ---------------------------------------------------------------------------
__global__ __launch_bounds__(256)
void msgx_kernel(const float* __restrict__ X,
                 const float* __restrict__ A,
                 float* __restrict__ msg)
{
    const int bidx = blockIdx.x;
    const int b  = bidx >> 3;
    const int j0 = (bidx & 7) * 16;
    const int h  = threadIdx.x;

    __shared__ float Ash[128][16];
    for (int idx = threadIdx.x; idx < 128 * 16; idx += 256) {
        int i  = idx >> 4;
        int jj = idx & 15;
        Ash[i][jj] = A[(b * 128 + i) * 128 + j0 + jj];
    }
    __syncthreads();

    float acc[16];
    #pragma unroll
    for (int jj = 0; jj < 16; ++jj) acc[jj] = 0.f;

    const float* Xb = X + (size_t)b * 128 * 256 + h;
    for (int i = 0; i < 128; ++i) {
        float xv = Xb[(size_t)i * 256];
        #pragma unroll
        for (int jj = 0; jj < 16; ++jj) acc[jj] += Ash[i][jj] * xv;
    }
    #pragma unroll
    for (int jj = 0; jj < 16; ++jj)
        msg[(size_t)(b * 128 + j0 + jj) * NC + h] = acc[jj];
}

// ---------------------------------------------------------------------------
// Generic small GEMM: Out(2048 x 256) = epilogue( In(2048 x K) @ W(K x 256) )
//   epilogue: v = relu(acc + bias[col]); if resid: v += (1+eps)*resid[row,col]
// Block tile 64x64, 256 threads, 4x4 per thread, k-chunk 16.
// grid = (32, 4)
// ---------------------------------------------------------------------------
template <int K>
__global__ __launch_bounds__(256)
void mlp_gemm_kernel(const float* __restrict__ In,
                     const float* __restrict__ W,
                     const float* __restrict__ bias,
                     const float* __restrict__ resid,
                     const float* __restrict__ epsp,
                     float* __restrict__ Out)
{
    const int r0 = blockIdx.x * 64;
    const int c0 = blockIdx.y * 64;
    const int tid = threadIdx.x;
    const int tx = tid & 15;    // col group (4 cols)
    const int ty = tid >> 4;    // row group (4 rows)

    __shared__ float As[16][68];   // [k][row], 68*4=272B rows (16B-aligned)
    __shared__ float Bs[16][64];

    float acc[4][4];
    #pragma unroll
    for (int r = 0; r < 4; ++r)
        #pragma unroll
        for (int c = 0; c < 4; ++c) acc[r][c] = 0.f;

    for (int kc = 0; kc < K; kc += 16) {
        {   // As: 64 rows x 16 k = 256 float4, one per thread (transposed store)
            int row = tid >> 2;
            int kq  = tid & 3;
            float4 v = *(const float4*)(In + (size_t)(r0 + row) * K + kc + kq * 4);
            As[kq * 4 + 0][row] = v.x;
            As[kq * 4 + 1][row] = v.y;
            As[kq * 4 + 2][row] = v.z;
            As[kq * 4 + 3][row] = v.w;
        }
        {   // Bs: 16 k x 64 cols = 256 float4
            int kl = tid >> 4;
            int h4 = tid & 15;
            *(float4*)&Bs[kl][h4 * 4] =
                *(const float4*)(W + (size_t)(kc + kl) * 256 + c0 + h4 * 4);
        }
        __syncthreads();

        #pragma unroll
        for (int kk = 0; kk < 16; ++kk) {
            float a[4], bb[4];
            *(float4*)a  = *(const float4*)&As[kk][ty * 4];
            *(float4*)bb = *(const float4*)&Bs[kk][tx * 4];
            #pragma unroll
            for (int r = 0; r < 4; ++r)
                #pragma unroll
                for (int c = 0; c < 4; ++c) acc[r][c] += a[r] * bb[c];
        }
        __syncthreads();
    }

    float xs = 0.f;
    if (epsp) xs = 1.f + *epsp;

    #pragma unroll
    for (int r = 0; r < 4; ++r) {
        int row = r0 + ty * 4 + r;
        #pragma unroll
        for (int c = 0; c < 4; ++c) {
            int col = c0 + tx * 4 + c;
            float v = fmaxf(acc[r][c] + bias[col], 0.f);
            if (resid) v += xs * resid[(size_t)row * 256 + col];
            Out[(size_t)row * 256 + col] = v;
        }
    }
}

// ---------------------------------------------------------------------------
// Launch
// ---------------------------------------------------------------------------
extern "C" void kernel_launch(void* const* d_in, const int* in_sizes, int n_in,
                              void* d_out, int out_size)
{
    const float* X   = (const float*)d_in[0];
    const float* E   = (const float*)d_in[1];
    const float* A   = (const float*)d_in[2];
    const float* eps = (const float*)d_in[3];
    const float* We  = (const float*)d_in[4];
    const float* be  = (const float*)d_in[5];
    const float* Wr  = (const float*)d_in[6];
    const float* br  = (const float*)d_in[7];
    const float* W0  = (const float*)d_in[8];
    const float* b0  = (const float*)d_in[9];
    const float* W1  = (const float*)d_in[10];
    const float* b1  = (const float*)d_in[11];
    float* out = (float*)d_out;

    void *pmsg, *pt, *pu;
    cudaGetSymbolAddress(&pmsg, g_msg);
    cudaGetSymbolAddress(&pt,  g_t);
    cudaGetSymbolAddress(&pu,  g_u);
    float* msg = (float*)pmsg;
    float* t   = (float*)pt;
    float* u   = (float*)pu;

    // Hot kernel: fused Em GEMM + A-weighted i-reduction -> msg_e
    edge_msg_kernel<<<NROWS, 256>>>(E, A, We, be, msg);
    // msg_x
    msgx_kernel<<<NB * 8, 256>>>(X, A, msg);
    // t = (1+eps)*X + relu(msg @ Wr + br)
    mlp_gemm_kernel<NC><<<dim3(32, 4), 256>>>(msg, Wr, br, X, eps, t);
    // u = relu(t @ W0 + b0)
    mlp_gemm_kernel<NH><<<dim3(32, 4), 256>>>(t, W0, b0, nullptr, nullptr, u);
    // out = relu(u @ W1 + b1)
    mlp_gemm_kernel<NH><<<dim3(32, 4), 256>>>(u, W1, b1, nullptr, nullptr, out);
}

// round 4
// speedup vs baseline: 1.8329x; 1.8329x over previous
#include <cuda_runtime.h>
#include <cstdint>
#include <cstddef>

// Shapes (fixed)
#define NB 16
#define NM 128
#define NH 256
#define NE 128
#define NC 384
#define NROWS 2048
#define EDGE_GRID 148

// Scratch
__device__ float g_msg[NROWS * NC];
__device__ float g_t[NROWS * NH];
__device__ float g_u[NROWS * NH];

// ---------------------------------------------------------------------------
// SMEM layout (floats) for edge kernel
//   Es: E tile [128 i][132 pitch]  (pitch%32==4 -> conflict-free A frags)
//   Ws: We     [128 e][136 pitch]  (pitch%32==8 -> conflict-free B frags)
// ---------------------------------------------------------------------------
#define ES_PITCH 132
#define WS_PITCH 136
#define SM_ES 0
#define SM_WS (128 * ES_PITCH)               // 16896
#define SM_AW (SM_WS + 128 * WS_PITCH)       // 34304
#define SM_RED (SM_AW + 256)                 // 34560
#define SM_FLOATS (SM_RED + 128)             // 34688
#define SM_BYTES (SM_FLOATS * 4)             // 138752

// ---------------------------------------------------------------------------
// helpers
// ---------------------------------------------------------------------------
__device__ __forceinline__ uint32_t f2tf(float x) {
    uint32_t r;
    asm("cvt.rna.tf32.f32 %0, %1;" : "=r"(r) : "f"(x));
    return r;
}
__device__ __forceinline__ uint4 cvt4(float4 v) {
    return make_uint4(f2tf(v.x), f2tf(v.y), f2tf(v.z), f2tf(v.w));
}
// m16n8k8 tf32 mma: D[i,f] += A(16x8, row-major) * B(8x8, col frag)
__device__ __forceinline__ void mma8(float* d, const uint32_t* a, const uint32_t* b) {
    asm volatile(
        "mma.sync.aligned.m16n8k8.row.col.f32.tf32.tf32.f32 "
        "{%0,%1,%2,%3}, {%4,%5,%6,%7}, {%8,%9}, {%0,%1,%2,%3};"
        : "+f"(d[0]), "+f"(d[1]), "+f"(d[2]), "+f"(d[3])
        : "r"(a[0]), "r"(a[1]), "r"(a[2]), "r"(a[3]),
          "r"(b[0]), "r"(b[1]));
}

// compute one k-quarter (32 e values = 4 ksteps) for this warp's 64x64 block
__device__ __forceinline__ void compute_quarter(const float* __restrict__ ap,
                                                const float* __restrict__ bp,
                                                float acc[4][8][4])
{
    #pragma unroll
    for (int ss = 0; ss < 4; ++ss) {
        uint32_t a[4][4];
        #pragma unroll
        for (int m = 0; m < 4; ++m) {
            const float* p = ap + m * (16 * ES_PITCH) + ss * 8;
            a[m][0] = __float_as_uint(p[0]);
            a[m][1] = __float_as_uint(p[8 * ES_PITCH]);
            a[m][2] = __float_as_uint(p[4]);
            a[m][3] = __float_as_uint(p[8 * ES_PITCH + 4]);
        }
        uint32_t bq[8][2];
        #pragma unroll
        for (int n = 0; n < 8; ++n) {
            const float* p = bp + ss * (8 * WS_PITCH) + n * 8;
            bq[n][0] = __float_as_uint(p[0]);
            bq[n][1] = __float_as_uint(p[4 * WS_PITCH]);
        }
        #pragma unroll
        for (int m = 0; m < 4; ++m)
            #pragma unroll
            for (int n = 0; n < 8; ++n)
                mma8(acc[m][n], a[m], bq[n]);
    }
}

// ---------------------------------------------------------------------------
// Edge kernel: persistent, tf32 mma.sync, rna-rounded operands.
// Per tile t=(b,j): D[i,f] = sum_e E[b,i,j,e]*We[e,f];
//                   msg_e[f] = sum_i A[b,i,j]*relu(D[i,f]+be[f])
// 128 threads: 4 warps = 2 row-groups x 2 col-groups, 64x64 each.
// E staged per-quarter: LDG(raw)->regs one stage ahead, cvt+STS, sync, compute.
// ---------------------------------------------------------------------------
__global__ __launch_bounds__(128, 1)
void edge_msg_mma(const float* __restrict__ E,
                  const float* __restrict__ A,
                  const float* __restrict__ We,
                  const float* __restrict__ be,
                  float* __restrict__ msg)
{
    extern __shared__ float sm[];
    float* Es  = sm + SM_ES;
    float* Ws  = sm + SM_WS;
    float* awb = sm + SM_AW;
    float* red = sm + SM_RED;

    const int tid  = threadIdx.x;
    const int lane = tid & 31;
    const int wid  = tid >> 5;
    const int rg   = wid >> 1;
    const int cg   = wid & 1;
    const int row0 = rg * 64;
    const int col0 = cg * 64;

    // bias fragments
    float be0[8], be1[8];
    #pragma unroll
    for (int n = 0; n < 8; ++n) {
        be0[n] = be[col0 + 8 * n + 2 * (lane & 3)];
        be1[n] = be[col0 + 8 * n + 2 * (lane & 3) + 1];
    }

    // We -> SMEM with rna rounding (once). e = tid>>5 + 4q, f = (tid&31)*4.
    {
        const float* wsrc = We + (size_t)(tid >> 5) * 128 + (tid & 31) * 4;
        float* wdst = Ws + (tid >> 5) * WS_PITCH + (tid & 31) * 4;
        #pragma unroll
        for (int q = 0; q < 32; ++q)
            *(uint4*)(wdst + q * (4 * WS_PITCH)) = cvt4(*(const float4*)(wsrc + q * 512));
    }

    const int t0  = blockIdx.x;
    const int ntl = (NROWS - t0 + EDGE_GRID - 1) / EDGE_GRID;

    // E quarter loader: quarter q covers e in [32q, 32q+32).
    // thread: e-chunk (tid&7)*4, rows i = (tid>>3) + 16r, r=0..7  -> 8 float4
    const int ech = (tid & 7) * 4;
    const int ir0 = tid >> 3;
    auto ldq = [&](float4* r, int t, int q) {
        const float* src = E + (size_t)(t >> 7) * 2097152
                             + (size_t)ir0 * 16384
                             + (size_t)(t & 127) * 128 + q * 32 + ech;
        #pragma unroll
        for (int rr = 0; rr < 8; ++rr)
            r[rr] = *(const float4*)(src + (size_t)rr * (16 * 16384));
    };
    float* qdst0 = Es + ir0 * ES_PITCH + ech;   // + q*32 + rr*16*ES_PITCH

    float4 pre[8];
    ldq(pre, t0, 0);
    float awreg = A[(size_t)(t0 >> 7) * 16384 + (size_t)tid * 128 + (t0 & 127)];

    float acc[4][8][4];
    #pragma unroll
    for (int m = 0; m < 4; ++m)
        #pragma unroll
        for (int n = 0; n < 8; ++n)
            #pragma unroll
            for (int q = 0; q < 4; ++q) acc[m][n][q] = 0.f;

    const float* aptr = Es + (row0 + (lane >> 2)) * ES_PITCH + (lane & 3);
    const float* bptr = Ws + (lane & 3) * WS_PITCH + col0 + (lane >> 2);

    for (int k = 0; k < ntl; ++k) {
        const int t = t0 + k * EDGE_GRID;
        const bool hn = (k + 1 < ntl);

        #pragma unroll
        for (int q = 0; q < 4; ++q) {
            // store staged quarter (cvt to tf32)
            float* qd = qdst0 + q * 32;
            #pragma unroll
            for (int rr = 0; rr < 8; ++rr)
                *(uint4*)(qd + rr * (16 * ES_PITCH)) = cvt4(pre[rr]);

            if (q == 0) {
                awb[(k & 1) * 128 + tid] = awreg;
                if (hn) {
                    const int tn = t + EDGE_GRID;
                    awreg = A[(size_t)(tn >> 7) * 16384 + (size_t)tid * 128 + (tn & 127)];
                }
            }
            // prefetch next quarter (or next tile's quarter 0)
            if (q < 3)       ldq(pre, t, q + 1);
            else if (hn)     ldq(pre, t + EDGE_GRID, 0);

            __syncthreads();
            compute_quarter(aptr + q * 32, bptr + q * (32 * WS_PITCH), acc);
            __syncthreads();
        }

        // ---- epilogue: bias+relu, weight by A, reduce over i ----
        {
            const float* aw = awb + (k & 1) * 128;
            float p0[8], p1[8];
            #pragma unroll
            for (int n = 0; n < 8; ++n) { p0[n] = 0.f; p1[n] = 0.f; }
            #pragma unroll
            for (int m = 0; m < 4; ++m) {
                float w0 = aw[row0 + 16 * m + (lane >> 2)];
                float w1 = aw[row0 + 16 * m + (lane >> 2) + 8];
                #pragma unroll
                for (int n = 0; n < 8; ++n) {
                    p0[n] += w0 * fmaxf(acc[m][n][0] + be0[n], 0.f)
                           + w1 * fmaxf(acc[m][n][2] + be0[n], 0.f);
                    p1[n] += w0 * fmaxf(acc[m][n][1] + be1[n], 0.f)
                           + w1 * fmaxf(acc[m][n][3] + be1[n], 0.f);
                    acc[m][n][0] = 0.f; acc[m][n][1] = 0.f;
                    acc[m][n][2] = 0.f; acc[m][n][3] = 0.f;
                }
            }
            #pragma unroll
            for (int off = 4; off < 32; off <<= 1) {
                #pragma unroll
                for (int n = 0; n < 8; ++n) {
                    p0[n] += __shfl_xor_sync(0xffffffffu, p0[n], off);
                    p1[n] += __shfl_xor_sync(0xffffffffu, p1[n], off);
                }
            }
            if (rg == 1 && lane < 4) {
                #pragma unroll
                for (int n = 0; n < 8; ++n) {
                    int f = col0 + 8 * n + 2 * lane;
                    red[f]     = p0[n];
                    red[f + 1] = p1[n];
                }
            }
            __syncthreads();
            if (rg == 0 && lane < 4) {
                #pragma unroll
                for (int n = 0; n < 8; ++n) {
                    int f = col0 + 8 * n + 2 * lane;
                    msg[(size_t)t * NC + NH + f]     = p0[n] + red[f];
                    msg[(size_t)t * NC + NH + f + 1] = p1[n] + red[f + 1];
                }
            }
            __syncthreads();
        }
    }
}

// ---------------------------------------------------------------------------
// msg_x[b,j,h] = sum_i A[b,i,j] * X[b,i,h] ; grid 256, 8 j per CTA
// ---------------------------------------------------------------------------
__global__ __launch_bounds__(256)
void msgx_kernel(const float* __restrict__ X,
                 const float* __restrict__ A,
                 float* __restrict__ msg)
{
    const int b  = blockIdx.x >> 4;
    const int j0 = (blockIdx.x & 15) * 8;
    const int h  = threadIdx.x;

    __shared__ float Ash[128][8];
    for (int idx = threadIdx.x; idx < 128 * 8; idx += 256) {
        int i = idx >> 3, jj = idx & 7;
        Ash[i][jj] = A[((size_t)(b * 128 + i)) * 128 + j0 + jj];
    }
    __syncthreads();

    float acc[8];
    #pragma unroll
    for (int jj = 0; jj < 8; ++jj) acc[jj] = 0.f;

    const float* Xb = X + (size_t)b * 128 * 256 + h;
    for (int i = 0; i < 128; ++i) {
        float xv = Xb[(size_t)i * 256];
        #pragma unroll
        for (int jj = 0; jj < 8; ++jj) acc[jj] += Ash[i][jj] * xv;
    }
    #pragma unroll
    for (int jj = 0; jj < 8; ++jj)
        msg[(size_t)(b * 128 + j0 + jj) * NC + h] = acc[jj];
}

// ---------------------------------------------------------------------------
// MLP GEMM: tile 64 rows x 32 cols, grid (32, 8) = 256 CTAs.
// ---------------------------------------------------------------------------
template <int K>
__global__ __launch_bounds__(256)
void mlp_gemm_kernel(const float* __restrict__ In,
                     const float* __restrict__ W,
                     const float* __restrict__ bias,
                     const float* __restrict__ resid,
                     const float* __restrict__ epsp,
                     float* __restrict__ Out)
{
    const int r0 = blockIdx.x * 64;
    const int c0 = blockIdx.y * 32;
    const int tid = threadIdx.x;
    const int tx = tid & 7;
    const int ty = tid >> 3;

    __shared__ float As[16][68];
    __shared__ float Bs[16][36];

    float acc[2][4];
    #pragma unroll
    for (int r = 0; r < 2; ++r)
        #pragma unroll
        for (int c = 0; c < 4; ++c) acc[r][c] = 0.f;

    for (int kc = 0; kc < K; kc += 16) {
        {
            int row = tid >> 2, kq = tid & 3;
            float4 v = *(const float4*)(In + (size_t)(r0 + row) * K + kc + kq * 4);
            As[kq * 4 + 0][row] = v.x;
            As[kq * 4 + 1][row] = v.y;
            As[kq * 4 + 2][row] = v.z;
            As[kq * 4 + 3][row] = v.w;
        }
        if (tid < 128) {
            int kl = tid >> 3, h4 = tid & 7;
            *(float4*)&Bs[kl][h4 * 4] =
                *(const float4*)(W + (size_t)(kc + kl) * 256 + c0 + h4 * 4);
        }
        __syncthreads();

        #pragma unroll
        for (int kk = 0; kk < 16; ++kk) {
            float a[2], bb[4];
            a[0] = As[kk][ty * 2 + 0];
            a[1] = As[kk][ty * 2 + 1];
            *(float4*)bb = *(const float4*)&Bs[kk][tx * 4];
            #pragma unroll
            for (int r = 0; r < 2; ++r)
                #pragma unroll
                for (int c = 0; c < 4; ++c) acc[r][c] += a[r] * bb[c];
        }
        __syncthreads();
    }

    float xs = 0.f;
    if (epsp) xs = 1.f + *epsp;

    #pragma unroll
    for (int r = 0; r < 2; ++r) {
        int row = r0 + ty * 2 + r;
        #pragma unroll
        for (int c = 0; c < 4; ++c) {
            int col = c0 + tx * 4 + c;
            float v = fmaxf(acc[r][c] + bias[col], 0.f);
            if (resid) v += xs * resid[(size_t)row * 256 + col];
            Out[(size_t)row * 256 + col] = v;
        }
    }
}

// ---------------------------------------------------------------------------
extern "C" void kernel_launch(void* const* d_in, const int* in_sizes, int n_in,
                              void* d_out, int out_size)
{
    const float* X   = (const float*)d_in[0];
    const float* E   = (const float*)d_in[1];
    const float* A   = (const float*)d_in[2];
    const float* eps = (const float*)d_in[3];
    const float* We  = (const float*)d_in[4];
    const float* be  = (const float*)d_in[5];
    const float* Wr  = (const float*)d_in[6];
    const float* br  = (const float*)d_in[7];
    const float* W0  = (const float*)d_in[8];
    const float* b0  = (const float*)d_in[9];
    const float* W1  = (const float*)d_in[10];
    const float* b1  = (const float*)d_in[11];
    float* out = (float*)d_out;

    void *pmsg, *pt, *pu;
    cudaGetSymbolAddress(&pmsg, g_msg);
    cudaGetSymbolAddress(&pt,  g_t);
    cudaGetSymbolAddress(&pu,  g_u);
    float* msg = (float*)pmsg;
    float* t   = (float*)pt;
    float* u   = (float*)pu;

    cudaFuncSetAttribute(edge_msg_mma,
                         cudaFuncAttributeMaxDynamicSharedMemorySize, SM_BYTES);

    edge_msg_mma<<<EDGE_GRID, 128, SM_BYTES>>>(E, A, We, be, msg);
    msgx_kernel<<<256, 256>>>(X, A, msg);
    mlp_gemm_kernel<NC><<<dim3(32, 8), 256>>>(msg, Wr, br, X, eps, t);
    mlp_gemm_kernel<NH><<<dim3(32, 8), 256>>>(t, W0, b0, nullptr, nullptr, u);
    mlp_gemm_kernel<NH><<<dim3(32, 8), 256>>>(u, W1, b1, nullptr, nullptr, out);
}

// round 5
// speedup vs baseline: 2.2021x; 1.2015x over previous
#include <cuda_runtime.h>
#include <cstdint>
#include <cstddef>

// Shapes (fixed)
#define NB 16
#define NM 128
#define NH 256
#define NE 128
#define NC 384
#define NROWS 2048
#define EDGE_GRID 148

// Scratch
__device__ float g_msg[NROWS * NC];
__device__ float g_t[NROWS * NH];
__device__ float g_u[NROWS * NH];

// ---------------------------------------------------------------------------
// SMEM layout (floats) for edge kernel
// ---------------------------------------------------------------------------
#define ES_PITCH 132
#define WS_PITCH 136
#define SM_ES 0
#define SM_WS (128 * ES_PITCH)               // 16896
#define SM_AW (SM_WS + 128 * WS_PITCH)       // 34304
#define SM_RED (SM_AW + 256)                 // 34560
#define SM_FLOATS (SM_RED + 128)             // 34688
#define SM_BYTES (SM_FLOATS * 4)             // 138752

// ---------------------------------------------------------------------------
// helpers
// ---------------------------------------------------------------------------
__device__ __forceinline__ uint32_t f2tf(float x) {
    uint32_t r;
    asm("cvt.rna.tf32.f32 %0, %1;" : "=r"(r) : "f"(x));
    return r;
}
__device__ __forceinline__ uint4 cvt4(float4 v) {
    return make_uint4(f2tf(v.x), f2tf(v.y), f2tf(v.z), f2tf(v.w));
}
// m16n8k8 tf32 mma
__device__ __forceinline__ void mma8(float* d, const uint32_t* a, const uint32_t* b) {
    asm volatile(
        "mma.sync.aligned.m16n8k8.row.col.f32.tf32.tf32.f32 "
        "{%0,%1,%2,%3}, {%4,%5,%6,%7}, {%8,%9}, {%0,%1,%2,%3};"
        : "+f"(d[0]), "+f"(d[1]), "+f"(d[2]), "+f"(d[3])
        : "r"(a[0]), "r"(a[1]), "r"(a[2]), "r"(a[3]),
          "r"(b[0]), "r"(b[1]));
}

// compute one k-quarter (32 e values = 4 ksteps) for a warp's 64x64 block
__device__ __forceinline__ void compute_quarter(const float* __restrict__ ap,
                                                const float* __restrict__ bp,
                                                float acc[4][8][4])
{
    #pragma unroll
    for (int ss = 0; ss < 4; ++ss) {
        uint32_t a[4][4];
        #pragma unroll
        for (int m = 0; m < 4; ++m) {
            const float* p = ap + m * (16 * ES_PITCH) + ss * 8;
            a[m][0] = __float_as_uint(p[0]);
            a[m][1] = __float_as_uint(p[8 * ES_PITCH]);
            a[m][2] = __float_as_uint(p[4]);
            a[m][3] = __float_as_uint(p[8 * ES_PITCH + 4]);
        }
        uint32_t bq[8][2];
        #pragma unroll
        for (int n = 0; n < 8; ++n) {
            const float* p = bp + ss * (8 * WS_PITCH) + n * 8;
            bq[n][0] = __float_as_uint(p[0]);
            bq[n][1] = __float_as_uint(p[4 * WS_PITCH]);
        }
        #pragma unroll
        for (int m = 0; m < 4; ++m)
            #pragma unroll
            for (int n = 0; n < 8; ++n)
                mma8(acc[m][n], a[m], bq[n]);
    }
}

// ---------------------------------------------------------------------------
// Edge kernel (as R4, minus provably-redundant syncs: 10 -> 5 per tile)
// ---------------------------------------------------------------------------
__global__ __launch_bounds__(128, 1)
void edge_msg_mma(const float* __restrict__ E,
                  const float* __restrict__ A,
                  const float* __restrict__ We,
                  const float* __restrict__ be,
                  float* __restrict__ msg)
{
    extern __shared__ float sm[];
    float* Es  = sm + SM_ES;
    float* Ws  = sm + SM_WS;
    float* awb = sm + SM_AW;
    float* red = sm + SM_RED;

    const int tid  = threadIdx.x;
    const int lane = tid & 31;
    const int wid  = tid >> 5;
    const int rg   = wid >> 1;
    const int cg   = wid & 1;
    const int row0 = rg * 64;
    const int col0 = cg * 64;

    float be0[8], be1[8];
    #pragma unroll
    for (int n = 0; n < 8; ++n) {
        be0[n] = be[col0 + 8 * n + 2 * (lane & 3)];
        be1[n] = be[col0 + 8 * n + 2 * (lane & 3) + 1];
    }

    // We -> SMEM with rna rounding (once)
    {
        const float* wsrc = We + (size_t)(tid >> 5) * 128 + (tid & 31) * 4;
        float* wdst = Ws + (tid >> 5) * WS_PITCH + (tid & 31) * 4;
        #pragma unroll
        for (int q = 0; q < 32; ++q)
            *(uint4*)(wdst + q * (4 * WS_PITCH)) = cvt4(*(const float4*)(wsrc + q * 512));
    }

    const int t0  = blockIdx.x;
    const int ntl = (NROWS - t0 + EDGE_GRID - 1) / EDGE_GRID;

    const int ech = (tid & 7) * 4;
    const int ir0 = tid >> 3;
    auto ldq = [&](float4* r, int t, int q) {
        const float* src = E + (size_t)(t >> 7) * 2097152
                             + (size_t)ir0 * 16384
                             + (size_t)(t & 127) * 128 + q * 32 + ech;
        #pragma unroll
        for (int rr = 0; rr < 8; ++rr)
            r[rr] = *(const float4*)(src + (size_t)rr * (16 * 16384));
    };
    float* qdst0 = Es + ir0 * ES_PITCH + ech;

    float4 pre[8];
    ldq(pre, t0, 0);
    float awreg = A[(size_t)(t0 >> 7) * 16384 + (size_t)tid * 128 + (t0 & 127)];

    float acc[4][8][4];
    #pragma unroll
    for (int m = 0; m < 4; ++m)
        #pragma unroll
        for (int n = 0; n < 8; ++n)
            #pragma unroll
            for (int q = 0; q < 4; ++q) acc[m][n][q] = 0.f;

    const float* aptr = Es + (row0 + (lane >> 2)) * ES_PITCH + (lane & 3);
    const float* bptr = Ws + (lane & 3) * WS_PITCH + col0 + (lane >> 2);

    for (int k = 0; k < ntl; ++k) {
        const int t = t0 + k * EDGE_GRID;
        const bool hn = (k + 1 < ntl);

        #pragma unroll
        for (int q = 0; q < 4; ++q) {
            float* qd = qdst0 + q * 32;
            #pragma unroll
            for (int rr = 0; rr < 8; ++rr)
                *(uint4*)(qd + rr * (16 * ES_PITCH)) = cvt4(pre[rr]);

            if (q == 0) {
                awb[(k & 1) * 128 + tid] = awreg;
                if (hn) {
                    const int tn = t + EDGE_GRID;
                    awreg = A[(size_t)(tn >> 7) * 16384 + (size_t)tid * 128 + (tn & 127)];
                }
            }
            if (q < 3)       ldq(pre, t, q + 1);
            else if (hn)     ldq(pre, t + EDGE_GRID, 0);

            __syncthreads();                       // STS(q) visible to all
            compute_quarter(aptr + q * 32, bptr + q * (32 * WS_PITCH), acc);
            // no trailing sync: next STS targets a disjoint column range
        }

        // ---- epilogue ----
        {
            const float* aw = awb + (k & 1) * 128;
            float p0[8], p1[8];
            #pragma unroll
            for (int n = 0; n < 8; ++n) { p0[n] = 0.f; p1[n] = 0.f; }
            #pragma unroll
            for (int m = 0; m < 4; ++m) {
                float w0 = aw[row0 + 16 * m + (lane >> 2)];
                float w1 = aw[row0 + 16 * m + (lane >> 2) + 8];
                #pragma unroll
                for (int n = 0; n < 8; ++n) {
                    p0[n] += w0 * fmaxf(acc[m][n][0] + be0[n], 0.f)
                           + w1 * fmaxf(acc[m][n][2] + be0[n], 0.f);
                    p1[n] += w0 * fmaxf(acc[m][n][1] + be1[n], 0.f)
                           + w1 * fmaxf(acc[m][n][3] + be1[n], 0.f);
                    acc[m][n][0] = 0.f; acc[m][n][1] = 0.f;
                    acc[m][n][2] = 0.f; acc[m][n][3] = 0.f;
                }
            }
            #pragma unroll
            for (int off = 4; off < 32; off <<= 1) {
                #pragma unroll
                for (int n = 0; n < 8; ++n) {
                    p0[n] += __shfl_xor_sync(0xffffffffu, p0[n], off);
                    p1[n] += __shfl_xor_sync(0xffffffffu, p1[n], off);
                }
            }
            if (rg == 1 && lane < 4) {
                #pragma unroll
                for (int n = 0; n < 8; ++n) {
                    int f = col0 + 8 * n + 2 * lane;
                    red[f]     = p0[n];
                    red[f + 1] = p1[n];
                }
            }
            __syncthreads();                       // red visible
            if (rg == 0 && lane < 4) {
                #pragma unroll
                for (int n = 0; n < 8; ++n) {
                    int f = col0 + 8 * n + 2 * lane;
                    msg[(size_t)t * NC + NH + f]     = p0[n] + red[f];
                    msg[(size_t)t * NC + NH + f + 1] = p1[n] + red[f + 1];
                }
            }
            // no trailing sync: red rewrite is fenced by next tile's 4 quarter syncs
        }
    }
}

// ---------------------------------------------------------------------------
// msg_x[b,j,h] = sum_i A[b,i,j] * X[b,i,h] ; grid 256, 8 j per CTA
// ---------------------------------------------------------------------------
__global__ __launch_bounds__(256)
void msgx_kernel(const float* __restrict__ X,
                 const float* __restrict__ A,
                 float* __restrict__ msg)
{
    const int b  = blockIdx.x >> 4;
    const int j0 = (blockIdx.x & 15) * 8;
    const int h  = threadIdx.x;

    __shared__ float Ash[128][8];
    for (int idx = threadIdx.x; idx < 128 * 8; idx += 256) {
        int i = idx >> 3, jj = idx & 7;
        Ash[i][jj] = A[((size_t)(b * 128 + i)) * 128 + j0 + jj];
    }
    __syncthreads();

    float acc[8];
    #pragma unroll
    for (int jj = 0; jj < 8; ++jj) acc[jj] = 0.f;

    const float* Xb = X + (size_t)b * 128 * 256 + h;
    for (int i = 0; i < 128; ++i) {
        float xv = Xb[(size_t)i * 256];
        #pragma unroll
        for (int jj = 0; jj < 8; ++jj) acc[jj] += Ash[i][jj] * xv;
    }
    #pragma unroll
    for (int jj = 0; jj < 8; ++jj)
        msg[(size_t)(b * 128 + j0 + jj) * NC + h] = acc[jj];
}

// ---------------------------------------------------------------------------
// MLP GEMM via tf32 mma: Out(2048x256) = relu(In(2048xK) @ W(Kx256) + bias)
//                        (+ (1+eps)*resid for layer 1)
// CTA: 128 thr, tile 64 rows x 64 cols; 4 warps of 32x32. grid (32, 4).
// K-chunks of 32, double-buffered SMEM, 1 sync per chunk.
// ---------------------------------------------------------------------------
#define MA_PITCH 36   // %32==4 -> conflict-free A frags
#define MB_PITCH 72   // %32==8 -> conflict-free B frags

template <int K>
__global__ __launch_bounds__(128)
void mlp_mma_kernel(const float* __restrict__ In,
                    const float* __restrict__ W,
                    const float* __restrict__ bias,
                    const float* __restrict__ resid,
                    const float* __restrict__ epsp,
                    float* __restrict__ Out)
{
    __shared__ float As[2][64 * MA_PITCH];
    __shared__ float Bs[2][32 * MB_PITCH];

    const int r0 = blockIdx.x * 64;
    const int c0 = blockIdx.y * 64;
    const int tid  = threadIdx.x;
    const int lane = tid & 31;
    const int wid  = tid >> 5;
    const int rg   = wid >> 1;
    const int cg   = wid & 1;
    const int wrow0 = rg * 32;
    const int wcol0 = cg * 32;

    // staging indices
    const int arow = tid >> 1;            // 0..63
    const int ak0  = (tid & 1) * 16;      // 0 or 16
    const int bk   = tid >> 2;            // 0..31
    const int bc0  = (tid & 3) * 16;      // 0,16,32,48

    const float* insrc = In + (size_t)(r0 + arow) * K + ak0;
    const float* wsrc  = W + (size_t)bk * 256 + c0 + bc0;

    float4 pin[4], pw[4];
    #pragma unroll
    for (int q = 0; q < 4; ++q) {
        pin[q] = *(const float4*)(insrc + q * 4);
        pw[q]  = *(const float4*)(wsrc + q * 4);
    }

    float acc[2][4][4];
    #pragma unroll
    for (int m = 0; m < 2; ++m)
        #pragma unroll
        for (int n = 0; n < 4; ++n)
            #pragma unroll
            for (int q = 0; q < 4; ++q) acc[m][n][q] = 0.f;

    const int NCH = K / 32;
    for (int kc = 0; kc < NCH; ++kc) {
        const int buf = kc & 1;
        // STS staged chunk
        float* ad = As[buf] + arow * MA_PITCH + ak0;
        float* bd = Bs[buf] + bk * MB_PITCH + bc0;
        #pragma unroll
        for (int q = 0; q < 4; ++q) {
            *(uint4*)(ad + q * 4) = cvt4(pin[q]);
            *(uint4*)(bd + q * 4) = cvt4(pw[q]);
        }
        // prefetch next chunk
        if (kc + 1 < NCH) {
            const float* ins = insrc + (kc + 1) * 32;
            const float* ws  = wsrc + (size_t)(kc + 1) * 32 * 256;
            #pragma unroll
            for (int q = 0; q < 4; ++q) {
                pin[q] = *(const float4*)(ins + q * 4);
                pw[q]  = *(const float4*)(ws + q * 4);
            }
        }
        __syncthreads();

        const float* ap = As[buf] + (wrow0 + (lane >> 2)) * MA_PITCH + (lane & 3);
        const float* bp = Bs[buf] + (lane & 3) * MB_PITCH + wcol0 + (lane >> 2);
        #pragma unroll
        for (int ss = 0; ss < 4; ++ss) {
            uint32_t a[2][4];
            #pragma unroll
            for (int m = 0; m < 2; ++m) {
                const float* p = ap + m * (16 * MA_PITCH) + ss * 8;
                a[m][0] = __float_as_uint(p[0]);
                a[m][1] = __float_as_uint(p[8 * MA_PITCH]);
                a[m][2] = __float_as_uint(p[4]);
                a[m][3] = __float_as_uint(p[8 * MA_PITCH + 4]);
            }
            uint32_t bq[4][2];
            #pragma unroll
            for (int n = 0; n < 4; ++n) {
                const float* p = bp + ss * (8 * MB_PITCH) + n * 8;
                bq[n][0] = __float_as_uint(p[0]);
                bq[n][1] = __float_as_uint(p[4 * MB_PITCH]);
            }
            #pragma unroll
            for (int m = 0; m < 2; ++m)
                #pragma unroll
                for (int n = 0; n < 4; ++n)
                    mma8(acc[m][n], a[m], bq[n]);
        }
        // no trailing sync: next STS targets the other buffer; barrier ordering
        // guarantees all warps finished the prior compute on that buffer.
    }

    float xs = 0.f;
    if (epsp) xs = 1.f + *epsp;

    #pragma unroll
    for (int m = 0; m < 2; ++m) {
        #pragma unroll
        for (int n = 0; n < 4; ++n) {
            int row = r0 + wrow0 + 16 * m + (lane >> 2);
            int col = c0 + wcol0 + 8 * n + 2 * (lane & 3);
            #pragma unroll
            for (int q = 0; q < 4; ++q) {
                int rr = row + (q >= 2 ? 8 : 0);
                int cc = col + (q & 1);
                float v = fmaxf(acc[m][n][q] + bias[cc], 0.f);
                if (resid) v += xs * resid[(size_t)rr * 256 + cc];
                Out[(size_t)rr * 256 + cc] = v;
            }
        }
    }
}

// ---------------------------------------------------------------------------
extern "C" void kernel_launch(void* const* d_in, const int* in_sizes, int n_in,
                              void* d_out, int out_size)
{
    const float* X   = (const float*)d_in[0];
    const float* E   = (const float*)d_in[1];
    const float* A   = (const float*)d_in[2];
    const float* eps = (const float*)d_in[3];
    const float* We  = (const float*)d_in[4];
    const float* be  = (const float*)d_in[5];
    const float* Wr  = (const float*)d_in[6];
    const float* br  = (const float*)d_in[7];
    const float* W0  = (const float*)d_in[8];
    const float* b0  = (const float*)d_in[9];
    const float* W1  = (const float*)d_in[10];
    const float* b1  = (const float*)d_in[11];
    float* out = (float*)d_out;

    void *pmsg, *pt, *pu;
    cudaGetSymbolAddress(&pmsg, g_msg);
    cudaGetSymbolAddress(&pt,  g_t);
    cudaGetSymbolAddress(&pu,  g_u);
    float* msg = (float*)pmsg;
    float* t   = (float*)pt;
    float* u   = (float*)pu;

    cudaFuncSetAttribute(edge_msg_mma,
                         cudaFuncAttributeMaxDynamicSharedMemorySize, SM_BYTES);

    edge_msg_mma<<<EDGE_GRID, 128, SM_BYTES>>>(E, A, We, be, msg);
    msgx_kernel<<<256, 256>>>(X, A, msg);
    mlp_mma_kernel<NC><<<dim3(32, 4), 128>>>(msg, Wr, br, X, eps, t);
    mlp_mma_kernel<NH><<<dim3(32, 4), 128>>>(t, W0, b0, nullptr, nullptr, u);
    mlp_mma_kernel<NH><<<dim3(32, 4), 128>>>(u, W1, b1, nullptr, nullptr, out);
}

// round 6
// speedup vs baseline: 2.7167x; 1.2337x over previous
#include <cuda_runtime.h>
#include <cstdint>
#include <cstddef>

// Shapes (fixed)
#define NB 16
#define NM 128
#define NH 256
#define NE 128
#define NC 384
#define NROWS 2048
#define EDGE_GRID 148

// Scratch
__device__ float g_msg[NROWS * NC];

// ---------------------------------------------------------------------------
// helpers
// ---------------------------------------------------------------------------
__device__ __forceinline__ uint32_t f2tf(float x) {
    uint32_t r;
    asm("cvt.rna.tf32.f32 %0, %1;" : "=r"(r) : "f"(x));
    return r;
}
__device__ __forceinline__ uint4 cvt4(float4 v) {
    return make_uint4(f2tf(v.x), f2tf(v.y), f2tf(v.z), f2tf(v.w));
}
__device__ __forceinline__ void mma8(float* d, const uint32_t* a, const uint32_t* b) {
    asm volatile(
        "mma.sync.aligned.m16n8k8.row.col.f32.tf32.tf32.f32 "
        "{%0,%1,%2,%3}, {%4,%5,%6,%7}, {%8,%9}, {%0,%1,%2,%3};"
        : "+f"(d[0]), "+f"(d[1]), "+f"(d[2]), "+f"(d[3])
        : "r"(a[0]), "r"(a[1]), "r"(a[2]), "r"(a[3]),
          "r"(b[0]), "r"(b[1]));
}

// ---------------------------------------------------------------------------
// Edge kernel SMEM layout (floats)
// ---------------------------------------------------------------------------
#define ES_PITCH 132
#define WS_PITCH 136
#define SM_ES 0
#define SM_WS (128 * ES_PITCH)               // 16896
#define SM_AW (SM_WS + 128 * WS_PITCH)       // 34304
#define SM_RED (SM_AW + 256)                 // 34560
#define SM_FLOATS (SM_RED + 384)             // 34944
#define SM_BYTES (SM_FLOATS * 4)             // 139776

// compute one k-quarter (32 e = 4 ksteps) for a warp's 32x64 block
__device__ __forceinline__ void compute_quarter(const float* __restrict__ ap,
                                                const float* __restrict__ bp,
                                                float acc[2][8][4])
{
    #pragma unroll
    for (int ss = 0; ss < 4; ++ss) {
        uint32_t a[2][4];
        #pragma unroll
        for (int m = 0; m < 2; ++m) {
            const float* p = ap + m * (16 * ES_PITCH) + ss * 8;
            a[m][0] = __float_as_uint(p[0]);
            a[m][1] = __float_as_uint(p[8 * ES_PITCH]);
            a[m][2] = __float_as_uint(p[4]);
            a[m][3] = __float_as_uint(p[8 * ES_PITCH + 4]);
        }
        uint32_t bq[8][2];
        #pragma unroll
        for (int n = 0; n < 8; ++n) {
            const float* p = bp + ss * (8 * WS_PITCH) + n * 8;
            bq[n][0] = __float_as_uint(p[0]);
            bq[n][1] = __float_as_uint(p[4 * WS_PITCH]);
        }
        #pragma unroll
        for (int m = 0; m < 2; ++m)
            #pragma unroll
            for (int n = 0; n < 8; ++n)
                mma8(acc[m][n], a[m], bq[n]);
    }
}

// ---------------------------------------------------------------------------
// Edge kernel: persistent, tf32 mma, 256 threads = 8 warps (4 rg x 2 cg).
// Per tile t=(b,j): D[i,f] = sum_e E[b,i,j,e]*We[e,f];
//                   msg_e[f] = sum_i A[b,i,j]*relu(D[i,f]+be[f])
// ---------------------------------------------------------------------------
__global__ __launch_bounds__(256, 1)
void edge_msg_mma(const float* __restrict__ E,
                  const float* __restrict__ A,
                  const float* __restrict__ We,
                  const float* __restrict__ be,
                  float* __restrict__ msg)
{
    extern __shared__ float sm[];
    float* Es  = sm + SM_ES;
    float* Ws  = sm + SM_WS;
    float* awb = sm + SM_AW;
    float* red = sm + SM_RED;

    const int tid  = threadIdx.x;
    const int lane = tid & 31;
    const int wid  = tid >> 5;
    const int rg   = wid >> 1;          // 0..3: rows rg*32..+31
    const int cg   = wid & 1;           // cols cg*64..+63
    const int row0 = rg * 32;
    const int col0 = cg * 64;

    float be0[8], be1[8];
    #pragma unroll
    for (int n = 0; n < 8; ++n) {
        be0[n] = be[col0 + 8 * n + 2 * (lane & 3)];
        be1[n] = be[col0 + 8 * n + 2 * (lane & 3) + 1];
    }

    // We -> SMEM (tf32). 256 threads: f-chunk (tid&31)*4, rows (tid>>5)+8q
    {
        const float* wsrc = We + (size_t)(tid >> 5) * 128 + (tid & 31) * 4;
        float* wdst = Ws + (tid >> 5) * WS_PITCH + (tid & 31) * 4;
        #pragma unroll
        for (int q = 0; q < 16; ++q)
            *(uint4*)(wdst + q * (8 * WS_PITCH)) = cvt4(*(const float4*)(wsrc + q * 1024));
    }

    const int t0  = blockIdx.x;
    const int ntl = (NROWS - t0 + EDGE_GRID - 1) / EDGE_GRID;

    // E quarter loader: 128 i x 32 e. thread: e-chunk (tid&7)*4, rows (tid>>3)+32r
    const int ech = (tid & 7) * 4;
    const int ir0 = tid >> 3;
    auto ldq = [&](float4* r, int t, int q) {
        const float* src = E + (size_t)(t >> 7) * 2097152
                             + (size_t)ir0 * 16384
                             + (size_t)(t & 127) * 128 + q * 32 + ech;
        #pragma unroll
        for (int rr = 0; rr < 4; ++rr)
            r[rr] = *(const float4*)(src + (size_t)rr * (32 * 16384));
    };
    float* qdst0 = Es + ir0 * ES_PITCH + ech;

    float4 pre[4];
    ldq(pre, t0, 0);
    float awreg = (tid < 128)
        ? A[(size_t)(t0 >> 7) * 16384 + (size_t)tid * 128 + (t0 & 127)] : 0.f;

    float acc[2][8][4];
    #pragma unroll
    for (int m = 0; m < 2; ++m)
        #pragma unroll
        for (int n = 0; n < 8; ++n)
            #pragma unroll
            for (int q = 0; q < 4; ++q) acc[m][n][q] = 0.f;

    const float* aptr = Es + (row0 + (lane >> 2)) * ES_PITCH + (lane & 3);
    const float* bptr = Ws + (lane & 3) * WS_PITCH + col0 + (lane >> 2);

    for (int k = 0; k < ntl; ++k) {
        const int t = t0 + k * EDGE_GRID;
        const bool hn = (k + 1 < ntl);

        #pragma unroll
        for (int q = 0; q < 4; ++q) {
            float* qd = qdst0 + q * 32;
            #pragma unroll
            for (int rr = 0; rr < 4; ++rr)
                *(uint4*)(qd + rr * (32 * ES_PITCH)) = cvt4(pre[rr]);

            if (q == 0 && tid < 128) {
                awb[(k & 1) * 128 + tid] = awreg;
                if (hn) {
                    const int tn = t + EDGE_GRID;
                    awreg = A[(size_t)(tn >> 7) * 16384 + (size_t)tid * 128 + (tn & 127)];
                }
            }
            if (q < 3)       ldq(pre, t, q + 1);
            else if (hn)     ldq(pre, t + EDGE_GRID, 0);

            __syncthreads();
            compute_quarter(aptr + q * 32, bptr + q * (32 * WS_PITCH), acc);
        }

        // ---- epilogue: bias+relu, weight by A, reduce over i ----
        {
            const float* aw = awb + (k & 1) * 128;
            float p0[8], p1[8];
            #pragma unroll
            for (int n = 0; n < 8; ++n) { p0[n] = 0.f; p1[n] = 0.f; }
            #pragma unroll
            for (int m = 0; m < 2; ++m) {
                float w0 = aw[row0 + 16 * m + (lane >> 2)];
                float w1 = aw[row0 + 16 * m + (lane >> 2) + 8];
                #pragma unroll
                for (int n = 0; n < 8; ++n) {
                    p0[n] += w0 * fmaxf(acc[m][n][0] + be0[n], 0.f)
                           + w1 * fmaxf(acc[m][n][2] + be0[n], 0.f);
                    p1[n] += w0 * fmaxf(acc[m][n][1] + be1[n], 0.f)
                           + w1 * fmaxf(acc[m][n][3] + be1[n], 0.f);
                    acc[m][n][0] = 0.f; acc[m][n][1] = 0.f;
                    acc[m][n][2] = 0.f; acc[m][n][3] = 0.f;
                }
            }
            #pragma unroll
            for (int off = 4; off < 32; off <<= 1) {
                #pragma unroll
                for (int n = 0; n < 8; ++n) {
                    p0[n] += __shfl_xor_sync(0xffffffffu, p0[n], off);
                    p1[n] += __shfl_xor_sync(0xffffffffu, p1[n], off);
                }
            }
            if (rg > 0 && lane < 4) {
                #pragma unroll
                for (int n = 0; n < 8; ++n) {
                    int f = col0 + 8 * n + 2 * lane;
                    red[(rg - 1) * 128 + f]     = p0[n];
                    red[(rg - 1) * 128 + f + 1] = p1[n];
                }
            }
            __syncthreads();
            if (rg == 0 && lane < 4) {
                #pragma unroll
                for (int n = 0; n < 8; ++n) {
                    int f = col0 + 8 * n + 2 * lane;
                    msg[(size_t)t * NC + NH + f] =
                        p0[n] + red[f] + red[128 + f] + red[256 + f];
                    msg[(size_t)t * NC + NH + f + 1] =
                        p1[n] + red[f + 1] + red[128 + f + 1] + red[256 + f + 1];
                }
            }
        }
    }
}

// ---------------------------------------------------------------------------
// msg_x[b,j,h] = sum_i A[b,i,j] * X[b,i,h] ; grid 256, 8 j per CTA
// ---------------------------------------------------------------------------
__global__ __launch_bounds__(256)
void msgx_kernel(const float* __restrict__ X,
                 const float* __restrict__ A,
                 float* __restrict__ msg)
{
    const int b  = blockIdx.x >> 4;
    const int j0 = (blockIdx.x & 15) * 8;
    const int h  = threadIdx.x;

    __shared__ float Ash[128][8];
    for (int idx = threadIdx.x; idx < 128 * 8; idx += 256) {
        int i = idx >> 3, jj = idx & 7;
        Ash[i][jj] = A[((size_t)(b * 128 + i)) * 128 + j0 + jj];
    }
    __syncthreads();

    float acc[8];
    #pragma unroll
    for (int jj = 0; jj < 8; ++jj) acc[jj] = 0.f;

    const float* Xb = X + (size_t)b * 128 * 256 + h;
    for (int i = 0; i < 128; ++i) {
        float xv = Xb[(size_t)i * 256];
        #pragma unroll
        for (int jj = 0; jj < 8; ++jj) acc[jj] += Ash[i][jj] * xv;
    }
    #pragma unroll
    for (int jj = 0; jj < 8; ++jj)
        msg[(size_t)(b * 128 + j0 + jj) * NC + h] = acc[jj];
}

// ---------------------------------------------------------------------------
// Fused MLP: one CTA owns 16 rows x all 256 cols; t,u stay in SMEM.
//   t = (1+eps)*X + relu(msg@Wr + br); u = relu(t@W0 + b0); out = relu(u@W1 + b1)
// 256 threads = 8 warps, warp tile 16x32 (n=4). grid 128.
// ---------------------------------------------------------------------------
#define FA_PITCH 388   // msg A tile pitch (%32==4)
#define FT_PITCH 260   // t/u pitch (%32==4)
#define FB_PITCH 264   // B chunk pitch (%32==8)
#define OF_TS (16 * FA_PITCH)            // 6208
#define OF_US (OF_TS + 16 * FT_PITCH)    // 10368
#define OF_BS (OF_US + 16 * FT_PITCH)    // 14528
#define FSM_FLOATS (OF_BS + 2 * 32 * FB_PITCH)   // 31424
#define FSM_BYTES (FSM_FLOATS * 4)               // 125696

// one GEMM phase: acc[n][q] += A(16 x 32*nch) @ W(32*nch x 256) [warp cols wcol0..+31]
__device__ __forceinline__ void fgemm(const float* __restrict__ Asm, int PA,
                                      const float* __restrict__ W,
                                      float* __restrict__ bs0,
                                      float* __restrict__ bs1,
                                      int nch, int tid, int lane, int wcol0,
                                      float acc[4][4])
{
    const int bk  = tid >> 3;
    const int bc0 = (tid & 7) * 4;
    const float* wsrc = W + (size_t)bk * 256 + bc0;

    float4 pw[8];
    #pragma unroll
    for (int q = 0; q < 8; ++q) pw[q] = *(const float4*)(wsrc + 32 * q);

    for (int kc = 0; kc < nch; ++kc) {
        float* bd = ((kc & 1) ? bs1 : bs0) + bk * FB_PITCH + bc0;
        #pragma unroll
        for (int q = 0; q < 8; ++q) *(uint4*)(bd + 32 * q) = cvt4(pw[q]);
        if (kc + 1 < nch) {
            const float* ws = wsrc + (size_t)(kc + 1) * 32 * 256;
            #pragma unroll
            for (int q = 0; q < 8; ++q) pw[q] = *(const float4*)(ws + 32 * q);
        }
        __syncthreads();

        const float* ap = Asm + (lane >> 2) * PA + (lane & 3) + kc * 32;
        const float* bp = ((kc & 1) ? bs1 : bs0) + (lane & 3) * FB_PITCH
                        + wcol0 + (lane >> 2);
        #pragma unroll
        for (int ss = 0; ss < 4; ++ss) {
            uint32_t a[4];
            const float* p = ap + ss * 8;
            a[0] = __float_as_uint(p[0]);
            a[1] = __float_as_uint(p[8 * PA]);
            a[2] = __float_as_uint(p[4]);
            a[3] = __float_as_uint(p[8 * PA + 4]);
            uint32_t bq[4][2];
            #pragma unroll
            for (int n = 0; n < 4; ++n) {
                const float* p2 = bp + ss * (8 * FB_PITCH) + n * 8;
                bq[n][0] = __float_as_uint(p2[0]);
                bq[n][1] = __float_as_uint(p2[4 * FB_PITCH]);
            }
            #pragma unroll
            for (int n = 0; n < 4; ++n) mma8(acc[n], a, bq[n]);
        }
        // no trailing sync: double-buffered; barrier order protects reuse
    }
}

__global__ __launch_bounds__(256)
void mlp_fused(const float* __restrict__ msg,
               const float* __restrict__ X,
               const float* __restrict__ epsp,
               const float* __restrict__ Wr, const float* __restrict__ br,
               const float* __restrict__ W0, const float* __restrict__ b0,
               const float* __restrict__ W1, const float* __restrict__ b1,
               float* __restrict__ Out)
{
    extern __shared__ float fsm[];
    float* Am  = fsm;
    float* Ts  = fsm + OF_TS;
    float* Us  = fsm + OF_US;
    float* bs0 = fsm + OF_BS;
    float* bs1 = fsm + OF_BS + 32 * FB_PITCH;

    const int r0   = blockIdx.x * 16;
    const int tid  = threadIdx.x;
    const int lane = tid & 31;
    const int wid  = tid >> 5;
    const int wcol0 = wid * 32;

    // stage msg rows (tf32): row tid>>4, cols (tid&15)*24 .. +23
    {
        const int row = tid >> 4;
        const int c0  = (tid & 15) * 24;
        const float* src = msg + (size_t)(r0 + row) * NC + c0;
        float* dst = Am + row * FA_PITCH + c0;
        #pragma unroll
        for (int q = 0; q < 6; ++q)
            *(uint4*)(dst + 4 * q) = cvt4(*(const float4*)(src + 4 * q));
    }
    __syncthreads();

    float acc[4][4];
    #pragma unroll
    for (int n = 0; n < 4; ++n)
        #pragma unroll
        for (int q = 0; q < 4; ++q) acc[n][q] = 0.f;

    // ---- layer 1: t = (1+eps)*X + relu(msg@Wr + br) ----
    fgemm(Am, FA_PITCH, Wr, bs0, bs1, 12, tid, lane, wcol0, acc);
    {
        const float epsv = 1.f + *epsp;
        #pragma unroll
        for (int n = 0; n < 4; ++n)
            #pragma unroll
            for (int q = 0; q < 4; ++q) {
                int row = (lane >> 2) + ((q & 2) ? 8 : 0);
                int col = wcol0 + 8 * n + 2 * (lane & 3) + (q & 1);
                float v = fmaxf(acc[n][q] + br[col], 0.f)
                        + epsv * X[(size_t)(r0 + row) * 256 + col];
                Ts[row * FT_PITCH + col] = __uint_as_float(f2tf(v));
                acc[n][q] = 0.f;
            }
    }
    __syncthreads();

    // ---- layer 2: u = relu(t@W0 + b0) ----
    fgemm(Ts, FT_PITCH, W0, bs0, bs1, 8, tid, lane, wcol0, acc);
    {
        #pragma unroll
        for (int n = 0; n < 4; ++n)
            #pragma unroll
            for (int q = 0; q < 4; ++q) {
                int row = (lane >> 2) + ((q & 2) ? 8 : 0);
                int col = wcol0 + 8 * n + 2 * (lane & 3) + (q & 1);
                float v = fmaxf(acc[n][q] + b0[col], 0.f);
                Us[row * FT_PITCH + col] = __uint_as_float(f2tf(v));
                acc[n][q] = 0.f;
            }
    }
    __syncthreads();

    // ---- layer 3: out = relu(u@W1 + b1) ----
    fgemm(Us, FT_PITCH, W1, bs0, bs1, 8, tid, lane, wcol0, acc);
    {
        #pragma unroll
        for (int n = 0; n < 4; ++n)
            #pragma unroll
            for (int q = 0; q < 4; ++q) {
                int row = (lane >> 2) + ((q & 2) ? 8 : 0);
                int col = wcol0 + 8 * n + 2 * (lane & 3) + (q & 1);
                Out[(size_t)(r0 + row) * 256 + col] = fmaxf(acc[n][q] + b1[col], 0.f);
            }
    }
}

// ---------------------------------------------------------------------------
extern "C" void kernel_launch(void* const* d_in, const int* in_sizes, int n_in,
                              void* d_out, int out_size)
{
    const float* X   = (const float*)d_in[0];
    const float* E   = (const float*)d_in[1];
    const float* A   = (const float*)d_in[2];
    const float* eps = (const float*)d_in[3];
    const float* We  = (const float*)d_in[4];
    const float* be  = (const float*)d_in[5];
    const float* Wr  = (const float*)d_in[6];
    const float* br  = (const float*)d_in[7];
    const float* W0  = (const float*)d_in[8];
    const float* b0  = (const float*)d_in[9];
    const float* W1  = (const float*)d_in[10];
    const float* b1  = (const float*)d_in[11];
    float* out = (float*)d_out;

    void* pmsg;
    cudaGetSymbolAddress(&pmsg, g_msg);
    float* msg = (float*)pmsg;

    cudaFuncSetAttribute(edge_msg_mma,
                         cudaFuncAttributeMaxDynamicSharedMemorySize, SM_BYTES);
    cudaFuncSetAttribute(mlp_fused,
                         cudaFuncAttributeMaxDynamicSharedMemorySize, FSM_BYTES);

    edge_msg_mma<<<EDGE_GRID, 256, SM_BYTES>>>(E, A, We, be, msg);
    msgx_kernel<<<256, 256>>>(X, A, msg);
    mlp_fused<<<128, 256, FSM_BYTES>>>(msg, X, eps, Wr, br, W0, b0, W1, b1, out);
}